// round 3
// baseline (speedup 1.0000x reference)
#include <cuda_runtime.h>
#include <cstdint>

// NodeDropout: out[e] = values[e] if neither endpoint is dropped, else 0.
// edge_index: int32 [2, E], values: f32 [E],
// nodes_flag: bool marshaled as int32 [N] (nonzero = dropped). Output: f32 [E].

__global__ __launch_bounds__(256)
void node_dropout_kernel(const int4* __restrict__ src4,
                         const int4* __restrict__ dst4,
                         const float4* __restrict__ vals,
                         const int* __restrict__ flag,
                         float4* __restrict__ out,
                         int n4) {
    int i = blockIdx.x * blockDim.x + threadIdx.x;
    if (i >= n4) return;

    int4 s = __ldg(&src4[i]);
    int4 d = __ldg(&dst4[i]);
    float4 v = __ldg(&vals[i]);

    // Flag gathers: 4 MB int32 array, L2-resident. drop = f[src] | f[dst].
    int k0 = __ldg(&flag[s.x]) | __ldg(&flag[d.x]);
    int k1 = __ldg(&flag[s.y]) | __ldg(&flag[d.y]);
    int k2 = __ldg(&flag[s.z]) | __ldg(&flag[d.z]);
    int k3 = __ldg(&flag[s.w]) | __ldg(&flag[d.w]);

    float4 o;
    o.x = k0 ? 0.0f : v.x;
    o.y = k1 ? 0.0f : v.y;
    o.z = k2 ? 0.0f : v.z;
    o.w = k3 ? 0.0f : v.w;
    out[i] = o;
}

extern "C" void kernel_launch(void* const* d_in, const int* in_sizes, int n_in,
                              void* d_out, int out_size) {
    // metadata order: edge_index [2, E] int32, values [E] f32, nodes_flag [N] int32
    const int* edge_index = (const int*)d_in[0];
    const float* values = (const float*)d_in[1];
    const int* nodes_flag = (const int*)d_in[2];
    float* out = (float*)d_out;

    int e = in_sizes[1];           // number of edges (= out_size)
    int n4 = e / 4;                // E = 20M, divisible by 4

    const int* src = edge_index;       // row 0
    const int* dst = edge_index + e;   // row 1

    int threads = 256;
    int blocks = (n4 + threads - 1) / threads;
    node_dropout_kernel<<<blocks, threads>>>((const int4*)src,
                                             (const int4*)dst,
                                             (const float4*)values,
                                             nodes_flag,
                                             (float4*)out, n4);
}

// round 4
// speedup vs baseline: 2.2401x; 2.2401x over previous
#include <cuda_runtime.h>
#include <cstdint>

// NodeDropout: out[e] = values[e] if neither endpoint is dropped, else 0.
// edge_index: int32 [2, E], values: f32 [E],
// nodes_flag: bool marshaled as int32 [N] (nonzero = dropped). Output: f32 [E].
//
// Strategy: pack flags into a 1-bit-per-node bitmask (125 KB for 1M nodes),
// stage the whole bitmask in shared memory per CTA, and do the random gathers
// as LDS instead of L1tex-pipe LDG (R3 showed L1=90.6% from gather wavefronts).

static constexpr int MAX_WORDS = 32768;  // supports up to 1,048,576 nodes
__device__ unsigned int g_bits[MAX_WORDS];

// ---- Kernel 1: pack int32 flags -> bitmask, one word per warp step ----
__global__ __launch_bounds__(256)
void pack_flags_kernel(const int* __restrict__ flag, int nflags, int nwords) {
    int warp = (blockIdx.x * blockDim.x + threadIdx.x) >> 5;
    int lane = threadIdx.x & 31;
    int nwarps = (gridDim.x * blockDim.x) >> 5;
    for (int w = warp; w < nwords; w += nwarps) {
        int idx = (w << 5) + lane;
        int f = (idx < nflags) ? flag[idx] : 0;
        unsigned int bits = __ballot_sync(0xFFFFFFFFu, f != 0);
        if (lane == 0) g_bits[w] = bits;
    }
}

// ---- Kernel 2: persistent, bitmask staged in smem ----
__global__ __launch_bounds__(1024, 1)
void node_dropout_kernel(const int4* __restrict__ src4,
                         const int4* __restrict__ dst4,
                         const float4* __restrict__ vals,
                         float4* __restrict__ out,
                         int n4, int nwords) {
    extern __shared__ unsigned int s_bits[];

    // Cooperative load of the bitmask into shared memory (coalesced).
    for (int w = threadIdx.x; w < nwords; w += blockDim.x)
        s_bits[w] = g_bits[w];
    __syncthreads();

    int stride = gridDim.x * blockDim.x;
    for (int i = blockIdx.x * blockDim.x + threadIdx.x; i < n4; i += stride) {
        int4 s = __ldg(&src4[i]);
        int4 d = __ldg(&dst4[i]);
        float4 v = __ldg(&vals[i]);

        unsigned int b0 = (s_bits[((unsigned)s.x) >> 5] >> (s.x & 31)) |
                          (s_bits[((unsigned)d.x) >> 5] >> (d.x & 31));
        unsigned int b1 = (s_bits[((unsigned)s.y) >> 5] >> (s.y & 31)) |
                          (s_bits[((unsigned)d.y) >> 5] >> (d.y & 31));
        unsigned int b2 = (s_bits[((unsigned)s.z) >> 5] >> (s.z & 31)) |
                          (s_bits[((unsigned)d.z) >> 5] >> (d.z & 31));
        unsigned int b3 = (s_bits[((unsigned)s.w) >> 5] >> (s.w & 31)) |
                          (s_bits[((unsigned)d.w) >> 5] >> (d.w & 31));

        float4 o;
        o.x = (b0 & 1u) ? 0.0f : v.x;
        o.y = (b1 & 1u) ? 0.0f : v.y;
        o.z = (b2 & 1u) ? 0.0f : v.z;
        o.w = (b3 & 1u) ? 0.0f : v.w;
        out[i] = o;
    }
}

extern "C" void kernel_launch(void* const* d_in, const int* in_sizes, int n_in,
                              void* d_out, int out_size) {
    // metadata order: edge_index [2, E] int32, values [E] f32, nodes_flag [N] int32
    const int* edge_index = (const int*)d_in[0];
    const float* values = (const float*)d_in[1];
    const int* nodes_flag = (const int*)d_in[2];
    float* out = (float*)d_out;

    int e = in_sizes[1];            // number of edges (= out_size)
    int nflags = in_sizes[2];       // number of nodes (1,000,000)
    int n4 = e / 4;                 // E divisible by 4
    int nwords = (nflags + 31) / 32;
    size_t smem_bytes = (size_t)nwords * sizeof(unsigned int);

    const int* src = edge_index;        // row 0
    const int* dst = edge_index + e;    // row 1

    // Pack flags -> bitmask
    pack_flags_kernel<<<256, 256>>>(nodes_flag, nflags, nwords);

    // Persistent main kernel: 1 CTA per SM (125 KB smem allows only one).
    int num_sms = 148;
    cudaDeviceGetAttribute(&num_sms, cudaDevAttrMultiProcessorCount, 0);
    cudaFuncSetAttribute(node_dropout_kernel,
                         cudaFuncAttributeMaxDynamicSharedMemorySize,
                         (int)smem_bytes);

    node_dropout_kernel<<<num_sms, 1024, smem_bytes>>>(
        (const int4*)src, (const int4*)dst, (const float4*)values,
        (float4*)out, n4, nwords);
}